// round 15
// baseline (speedup 1.0000x reference)
#include <cuda_runtime.h>
#include <cuda_bf16.h>
#include <cstdint>

// HorizontalDilation: out[r][c] = max(0, max_{d=-7..7} in[r][c+d]), zero padding.
// Window k=15. Zero padding + final relu => OOB values can be treated as 0.0f.
//
// Round-15: aligned 128-col warp chunks (fix misaligned 448B store regions).
//  - 4096/128 = 32 exact chunks: ALL 32 lanes store 4 cols -> every warp store
//    is an aligned, fully-covered 512B region. No split cache lines, no idle
//    store lanes, no bounds predicates on main loads/stores.
//  - Halo: lanes 0,1 also load left groups (-2,-1), lanes 2,3 load right
//    groups (32,33). Edge lanes 0,1,30,31 get halo aggregates via indexed
//    __shfl_sync broadcasts; interior lanes use the usual up/down shuffles.
//  - 4 rows/warp; 8 loads (4 main + 4 halo) batched asm-volatile => real MLP.
//  - Input loads carry L2 evict_last policy; stores are __stcs (evict-first).

#define IMG_W 4096
#define IMG_H 4096
#define COLS_PER_WARP 128
#define WARPS_PER_BLOCK 4
#define THREADS (WARPS_PER_BLOCK * 32)   // 128
#define ROWS_PER_WARP 4

// Unconditional 128-bit load with L2 cache-hint policy (always in-bounds).
#define LDG4(vv, ptr, pol)                                                  \
    asm volatile(                                                           \
        "ld.global.nc.L2::cache_hint.v4.f32 {%0, %1, %2, %3}, [%4], %5;"    \
        : "=f"((vv).x), "=f"((vv).y), "=f"((vv).z), "=f"((vv).w)            \
        : "l"(ptr), "l"(pol))

// Predicated 128-bit load (halo): pred==0 => zeros, NO memory access.
#define LDG4_PRED(vv, ptr, predu, pol)                                      \
    asm volatile("{\n\t"                                                    \
        ".reg .pred p;\n\t"                                                 \
        "setp.ne.u32 p, %5, 0;\n\t"                                         \
        "mov.f32 %0, 0f00000000;\n\t"                                       \
        "mov.f32 %1, 0f00000000;\n\t"                                       \
        "mov.f32 %2, 0f00000000;\n\t"                                       \
        "mov.f32 %3, 0f00000000;\n\t"                                       \
        "@p ld.global.nc.L2::cache_hint.v4.f32 {%0, %1, %2, %3}, [%4], %6;\n\t" \
        "}"                                                                 \
        : "=f"((vv).x), "=f"((vv).y), "=f"((vv).z), "=f"((vv).w)            \
        : "l"(ptr), "r"(predu), "l"(pol))

__global__ __launch_bounds__(THREADS, 6)
void HorizontalDilation_kernel(const float* __restrict__ in, float* __restrict__ out) {
    const unsigned FULL = 0xffffffffu;
    const int lane = threadIdx.x & 31;
    const int warp = threadIdx.x >> 5;
    const int W    = blockIdx.x * COLS_PER_WARP;                 // chunk base col
    const int row0 = (blockIdx.y * WARPS_PER_BLOCK + warp) * ROWS_PER_WARP;

    // Halo assignment: lane0 -> group -2 (col W-8), lane1 -> group -1 (W-4),
    // lane2 -> group 32 (W+128), lane3 -> group 33 (W+132). Others: none.
    const int hcol = (lane < 2) ? (W - 8 + 4 * lane) : (W + 120 + 4 * lane);
    const unsigned hpred =
        (lane < 2) ? (hcol >= 0 ? 1u : 0u)
                   : ((lane < 4) && (hcol < IMG_W) ? 1u : 0u);

    uint64_t pol;
    asm volatile("createpolicy.fractional.L2::evict_last.b64 %0, 1.0;" : "=l"(pol));

    const float* __restrict__ p  = in  + (size_t)row0 * IMG_W + W + 4 * lane;
    const float* __restrict__ ph = in  + (size_t)row0 * IMG_W + hcol;
    float*       __restrict__ q  = out + (size_t)row0 * IMG_W + W + 4 * lane;

    // Batch all 8 loads (4 main + 4 halo) back-to-back: real SASS MLP.
    float4 v0, v1, v2, v3, h0, h1, h2, h3;
    LDG4(v0, p + 0 * (size_t)IMG_W, pol);
    LDG4(v1, p + 1 * (size_t)IMG_W, pol);
    LDG4(v2, p + 2 * (size_t)IMG_W, pol);
    LDG4(v3, p + 3 * (size_t)IMG_W, pol);
    LDG4_PRED(h0, ph + 0 * (size_t)IMG_W, hpred, pol);
    LDG4_PRED(h1, ph + 1 * (size_t)IMG_W, hpred, pol);
    LDG4_PRED(h2, ph + 2 * (size_t)IMG_W, hpred, pol);
    LDG4_PRED(h3, ph + 3 * (size_t)IMG_W, hpred, pol);

    const float4 v[ROWS_PER_WARP] = {v0, v1, v2, v3};
    const float4 h[ROWS_PER_WARP] = {h0, h1, h2, h3};

    #pragma unroll
    for (int i = 0; i < ROWS_PER_WARP; i++) {
        const float4 a  = v[i];
        const float4 ha = h[i];

        // Main-group aggregates (group index == lane).
        const float suf1 = a.w;
        const float suf2 = fmaxf(a.z, suf1);
        const float suf3 = fmaxf(a.y, suf2);
        const float m4   = fmaxf(a.x, suf3);
        const float pre1 = a.x;
        const float pre2 = fmaxf(pre1, a.y);
        const float pre3 = fmaxf(pre2, a.z);

        // Halo-group aggregates (meaningful in lanes 0..3 only).
        const float hsuf1 = ha.w;
        const float hsuf2 = fmaxf(ha.z, hsuf1);
        const float hsuf3 = fmaxf(ha.y, hsuf2);
        const float hm4   = fmaxf(ha.x, hsuf3);
        const float hpre1 = ha.x;
        const float hpre2 = fmaxf(hpre1, ha.y);
        const float hpre3 = fmaxf(hpre2, ha.z);

        // Generic neighbor shuffles (interior lanes).
        const float sU1 = __shfl_up_sync  (FULL, suf1, 2);
        const float sU2 = __shfl_up_sync  (FULL, suf2, 2);
        const float sU3 = __shfl_up_sync  (FULL, suf3, 2);
        const float mU  = __shfl_up_sync  (FULL, m4,   1);
        const float mD  = __shfl_down_sync(FULL, m4,   1);
        const float pD1 = __shfl_down_sync(FULL, pre1, 2);
        const float pD2 = __shfl_down_sync(FULL, pre2, 2);
        const float pD3 = __shfl_down_sync(FULL, pre3, 2);

        // Halo broadcasts for edge lanes.
        const float hm4_1  = __shfl_sync(FULL, hm4,   1);  // group -1 m4  (lane 0)
        const float hm4_2  = __shfl_sync(FULL, hm4,   2);  // group 32 m4  (lane 31)
        const float hp1_2  = __shfl_sync(FULL, hpre1, 2);  // group 32 pre (lane 30)
        const float hp2_2  = __shfl_sync(FULL, hpre2, 2);
        const float hp3_2  = __shfl_sync(FULL, hpre3, 2);
        const float hp1_3  = __shfl_sync(FULL, hpre1, 3);  // group 33 pre (lane 31)
        const float hp2_3  = __shfl_sync(FULL, hpre2, 3);
        const float hp3_3  = __shfl_sync(FULL, hpre3, 3);

        // Effective per-lane sources. Lanes 0,1 use their OWN halo sufs
        // (groups -2,-1); lane 0's left-neighbor m4 is lane 1's halo.
        const float s1 = (lane >= 2) ? sU1 : hsuf1;
        const float s2 = (lane >= 2) ? sU2 : hsuf2;
        const float s3 = (lane >= 2) ? sU3 : hsuf3;
        const float mUe = (lane == 0)  ? hm4_1 : mU;
        const float mDe = (lane == 31) ? hm4_2 : mD;
        const float p1 = (lane <= 29) ? pD1 : ((lane == 30) ? hp1_2 : hp1_3);
        const float p2 = (lane <= 29) ? pD2 : ((lane == 30) ? hp2_2 : hp2_3);
        const float p3 = (lane <= 29) ? pD3 : ((lane == 30) ? hp3_2 : hp3_3);

        // Windows for outputs at cols W+4*lane+j:
        //  j=0: s3 | mUe | m4 | mDe ; j=1: s2 | core | p1 ; j=2: s1 | core | p2
        //  j=3: core | p3   (relu folded into core)
        const float core = fmaxf(fmaxf(mUe, m4), fmaxf(mDe, 0.f));
        float4 o;
        o.x = fmaxf(core, s3);
        o.y = fmaxf(fmaxf(core, s2), p1);
        o.z = fmaxf(fmaxf(core, s1), p2);
        o.w = fmaxf(core, p3);

        // ALL lanes store: aligned, fully-covered 512B per warp-row.
        __stcs((float4*)(q + (size_t)i * IMG_W), o);
    }
}

extern "C" void kernel_launch(void* const* d_in, const int* in_sizes, int n_in,
                              void* d_out, int out_size) {
    const float* img = (const float*)d_in[0];
    float* outp = (float*)d_out;
    (void)in_sizes; (void)n_in; (void)out_size;

    // 32 chunks of 128 cols; 4096 rows / (4 warps x 4 rows) = 256 blocks in y.
    dim3 grid(32, IMG_H / (WARPS_PER_BLOCK * ROWS_PER_WARP));   // (32, 256)
    dim3 block(THREADS);
    HorizontalDilation_kernel<<<grid, block>>>(img, outp);
}

// round 16
// speedup vs baseline: 1.0980x; 1.0980x over previous
#include <cuda_runtime.h>
#include <cuda_bf16.h>
#include <cstdint>

// HorizontalDilation: out[r][c] = max(0, max_{d=-7..7} in[r][c+d]), zero padding.
// Window k=15. Zero padding + final relu => OOB values can be treated as 0.0f.
//
// Round-16: 8 cols/lane via native 256-bit loads (LDG.256; ptxas round-13
// error message confirmed ld...v8.b32 exists on sm_100).
//  - Lane l owns cols col0..col0+7, col0 = 240*chunk - 8 + 8*l: one v8.b32
//    load = warp-contiguous 1KB, zero wavefront amplification.
//  - Read amplification 256/240 = 1.067x (vs 1.143x in the 4-col scheme).
//  - Round-3-verified shuffle math: suf1..7 / pre1..7 / m8, 14 shuffles per
//    8 outputs; lanes 1..30 store (two STG.128 each), 18 chunks x 240 cover
//    a row with the overhang predicated off (8 | 4096 -> group fully in/out).
//  - 2 rows/warp, loads batched asm-volatile; evict_last policy on loads,
//    __stcs stores.

#define IMG_W 4096
#define IMG_H 4096
#define OUT_PER_WARP 240
#define WARPS_PER_BLOCK 6
#define THREADS (WARPS_PER_BLOCK * 32)   // 192
#define ROWS_PER_WARP 2

// Predicated 256-bit load with L2 cache-hint. pred==0 => zeros, NO access.
#define LDG8_PRED(r, ptr, predu, pol)                                        \
    asm volatile("{\n\t"                                                     \
        ".reg .pred p;\n\t"                                                  \
        "setp.ne.u32 p, %9, 0;\n\t"                                          \
        "mov.b32 %0, 0;\n\t"                                                 \
        "mov.b32 %1, 0;\n\t"                                                 \
        "mov.b32 %2, 0;\n\t"                                                 \
        "mov.b32 %3, 0;\n\t"                                                 \
        "mov.b32 %4, 0;\n\t"                                                 \
        "mov.b32 %5, 0;\n\t"                                                 \
        "mov.b32 %6, 0;\n\t"                                                 \
        "mov.b32 %7, 0;\n\t"                                                 \
        "@p ld.global.nc.L2::cache_hint.v8.b32 "                             \
        "{%0, %1, %2, %3, %4, %5, %6, %7}, [%8], %10;\n\t"                   \
        "}"                                                                  \
        : "=r"((r)[0]), "=r"((r)[1]), "=r"((r)[2]), "=r"((r)[3]),            \
          "=r"((r)[4]), "=r"((r)[5]), "=r"((r)[6]), "=r"((r)[7])             \
        : "l"(ptr), "r"(predu), "l"(pol))

__global__ __launch_bounds__(THREADS, 6)
void HorizontalDilation_kernel(const float* __restrict__ in, float* __restrict__ out) {
    const unsigned FULL = 0xffffffffu;
    const int lane  = threadIdx.x & 31;
    const int warp  = threadIdx.x >> 5;
    const int chunk = blockIdx.x * WARPS_PER_BLOCK + warp;      // 0..17
    const int row0  = blockIdx.y * ROWS_PER_WARP;
    const int col0  = chunk * OUT_PER_WARP - 8 + 8 * lane;      // lane's 8-col group

    // 8 | IMG_W -> group fully in-bounds or fully out (single predicate).
    const bool inb = (col0 >= 0) & (col0 + 8 <= IMG_W);
    const unsigned predu = inb ? 1u : 0u;
    const bool wr  = inb & (lane >= 1) & (lane <= 30);

    uint64_t pol;
    asm volatile("createpolicy.fractional.L2::evict_last.b64 %0, 1.0;" : "=l"(pol));

    const float* __restrict__ p = in  + (size_t)row0 * IMG_W + col0;
    float*       __restrict__ q = out + (size_t)row0 * IMG_W + col0;

    // Both row-loads issued back-to-back (asm volatile => not sinkable).
    uint32_t r0[8], r1[8];
    LDG8_PRED(r0, p + 0 * (size_t)IMG_W, predu, pol);
    LDG8_PRED(r1, p + 1 * (size_t)IMG_W, predu, pol);

    #pragma unroll
    for (int i = 0; i < ROWS_PER_WARP; i++) {
        const uint32_t* r = (i == 0) ? r0 : r1;
        const float a0 = __uint_as_float(r[0]);
        const float a1 = __uint_as_float(r[1]);
        const float a2 = __uint_as_float(r[2]);
        const float a3 = __uint_as_float(r[3]);
        const float a4 = __uint_as_float(r[4]);
        const float a5 = __uint_as_float(r[5]);
        const float a6 = __uint_as_float(r[6]);
        const float a7 = __uint_as_float(r[7]);

        // Suffix maxes suf_i = max of last i elems; prefix pre_i = first i.
        const float suf1 = a7;
        const float suf2 = fmaxf(a6, suf1);
        const float suf3 = fmaxf(a5, suf2);
        const float suf4 = fmaxf(a4, suf3);
        const float suf5 = fmaxf(a3, suf4);
        const float suf6 = fmaxf(a2, suf5);
        const float suf7 = fmaxf(a1, suf6);
        const float m8   = fmaxf(a0, suf7);
        const float pre1 = a0;
        const float pre2 = fmaxf(pre1, a1);
        const float pre3 = fmaxf(pre2, a2);
        const float pre4 = fmaxf(pre3, a3);
        const float pre5 = fmaxf(pre4, a4);
        const float pre6 = fmaxf(pre5, a5);
        const float pre7 = fmaxf(pre6, a6);

        // Neighbor aggregates (14 shuffles for 8 outputs).
        const float sU1 = __shfl_up_sync(FULL, suf1, 1);
        const float sU2 = __shfl_up_sync(FULL, suf2, 1);
        const float sU3 = __shfl_up_sync(FULL, suf3, 1);
        const float sU4 = __shfl_up_sync(FULL, suf4, 1);
        const float sU5 = __shfl_up_sync(FULL, suf5, 1);
        const float sU6 = __shfl_up_sync(FULL, suf6, 1);
        const float sU7 = __shfl_up_sync(FULL, suf7, 1);
        const float pD1 = __shfl_down_sync(FULL, pre1, 1);
        const float pD2 = __shfl_down_sync(FULL, pre2, 1);
        const float pD3 = __shfl_down_sync(FULL, pre3, 1);
        const float pD4 = __shfl_down_sync(FULL, pre4, 1);
        const float pD5 = __shfl_down_sync(FULL, pre5, 1);
        const float pD6 = __shfl_down_sync(FULL, pre6, 1);
        const float pD7 = __shfl_down_sync(FULL, pre7, 1);

        // out[j] window [col0+j-7, col0+j+7]:
        //   j=0: suf7[l-1] | m8 ; j=1..6: suf_{7-j}[l-1] | m8 | pre_j[l+1]
        //   j=7: m8 | pre7[l+1]   (relu folded via m8r)
        const float m8r = fmaxf(m8, 0.f);
        float4 oa, ob;
        oa.x = fmaxf(m8r, sU7);
        oa.y = fmaxf(fmaxf(m8r, sU6), pD1);
        oa.z = fmaxf(fmaxf(m8r, sU5), pD2);
        oa.w = fmaxf(fmaxf(m8r, sU4), pD3);
        ob.x = fmaxf(fmaxf(m8r, sU3), pD4);
        ob.y = fmaxf(fmaxf(m8r, sU2), pD5);
        ob.z = fmaxf(fmaxf(m8r, sU1), pD6);
        ob.w = fmaxf(m8r, pD7);

        if (wr) {
            float* qo = q + (size_t)i * IMG_W;
            __stcs((float4*)qo, oa);
            __stcs((float4*)(qo + 4), ob);
        }
    }
}

extern "C" void kernel_launch(void* const* d_in, const int* in_sizes, int n_in,
                              void* d_out, int out_size) {
    const float* img = (const float*)d_in[0];
    float* outp = (float*)d_out;
    (void)in_sizes; (void)n_in; (void)out_size;

    // 18 chunks/row = 3 blocks x 6 warps; 4096/2 = 2048 row-pairs.
    dim3 grid(3, IMG_H / ROWS_PER_WARP);   // (3, 2048)
    dim3 block(THREADS);
    HorizontalDilation_kernel<<<grid, block>>>(img, outp);
}